// round 15
// baseline (speedup 1.0000x reference)
#include <cuda_runtime.h>

// KAN 1-D conv, B=32 I=8 O=32 W=8192 K=5 Wo=8188, 9 channels (silu + 8 cubic B-splines).
// R15: R14 (8o x 8w tile, TILE_W=256, work stealing) with I_CHUNK=1 -> smem 55.4KB
// -> 4 blocks/SM, 592 persistent blocks: better job tail (1.73 -> makespan 2) and
// a 4th warp/SMSP for issue rate.

#define B_DIM 32
#define I_DIM 8
#define O_DIM 32
#define W_IN 8192
#define KSZ 5
#define W_OUT (W_IN - KSZ + 1)   // 8188
#define NC 9
#define TILE_W 256
#define HALF_W 128
#define FP (TILE_W + KSZ - 1)    // 260
#define NTHREADS 128
#define NTILES ((W_OUT + TILE_W - 1) / TILE_W)   // 32
#define NJOBS (NTILES * B_DIM)                   // 1024
#define I_CHUNK 1
#define N_PHASE (I_DIM / I_CHUNK)   // 8
#define NSM 148
#define GRID_BLOCKS (NSM * 4)       // 592 persistent-ish blocks

__host__ __device__ constexpr float gridc(int j) {
    return (float)(j - 3) * 0.4f - 1.0f;
}

#define WC_ELEMS (I_DIM * KSZ * NC * O_DIM)    // 11520 floats = 46080 B
#define FS_ELEMS (I_CHUNK * NC * FP)           // 2340 floats  = 9360 B
#define SMEM_FLOATS (WC_ELEMS + FS_ELEMS)      // 13860 -> 55440 B (4 blocks/SM)

__device__ int g_tile_ctr;

__device__ __forceinline__ unsigned long long splat2(float f) {
    unsigned long long r;
    asm("mov.b64 %0, {%1, %1};" : "=l"(r) : "r"(__float_as_uint(f)));
    return r;
}
__device__ __forceinline__ void ffma2(unsigned long long& d,
                                      unsigned long long a,
                                      unsigned long long b) {
    asm("fma.rn.f32x2 %0, %1, %2, %0;" : "+l"(d) : "l"(a), "l"(b));
}
__device__ __forceinline__ float lo32(unsigned long long v) {
    return __uint_as_float((unsigned)(v & 0xffffffffull));
}
__device__ __forceinline__ float hi32(unsigned long long v) {
    return __uint_as_float((unsigned)(v >> 32));
}

__global__ void reset_ctr() { g_tile_ctr = 0; }

__global__ __launch_bounds__(NTHREADS, 4)
void kan_conv1d_kernel(const float* __restrict__ x,
                       const float* __restrict__ base_weight,
                       const float* __restrict__ spline_weight,
                       const float* __restrict__ spline_scaler,
                       float* __restrict__ out)
{
    extern __shared__ float smem[];
    float* Wc = smem;                 // [I][K][NC][O]  o contiguous
    float* Fs = smem + WC_ELEMS;      // [NC][FP]
    __shared__ int s_job;

    const int tid = threadIdx.x;

    // ---- Fuse weights into smem ONCE per block (amortized over ~1.7 jobs) ----
    for (int idx = tid; idx < O_DIM * I_DIM * KSZ; idx += NTHREADS) {
        int k = idx % KSZ;
        int r = idx / KSZ;
        int i = r % I_DIM;
        int o = r / I_DIM;
        float bw = base_weight[idx];
        float sc = spline_scaler[idx];
        float* dst = &Wc[((i * KSZ + k) * NC) * O_DIM + o];
        dst[0] = bw;
        const float* sw = &spline_weight[idx * 8];
        #pragma unroll
        for (int c = 0; c < 8; c++)
            dst[(c + 1) * O_DIM] = sw[c] * sc;
    }

    const int wt = tid & 31;      // 32 w-lanes (warp-uniform og)
    const int og = tid >> 5;      // 4 o-groups of 8 o, one per warp
    const int o0 = og * 8;

    // ---- Job loop: steal (b, tile) pairs from the global counter ----
    while (true) {
        // Barrier: (a) previous job's MAC done before Fs/s_job are overwritten,
        // (b) weight fuse done before first MAC.
        __syncthreads();
        if (tid == 0) s_job = atomicAdd(&g_tile_ctr, 1);
        __syncthreads();
        const int job = s_job;
        if (job >= NJOBS) break;

        const int b  = job >> 5;              // NTILES = 32
        const int w0 = (job & 31) * TILE_W;

        // acc[g][p][u]: w-group g, o-pair p = (o0+2p, o0+2p+1), w = wt*4+u+128g
        unsigned long long acc[2][4][4];
        #pragma unroll
        for (int g = 0; g < 2; g++)
            #pragma unroll
            for (int p = 0; p < 4; p++)
                #pragma unroll
                for (int u = 0; u < 4; u++)
                    acc[g][p][u] = 0ull;

        #pragma unroll 1
        for (int i = 0; i < I_DIM; i++) {
            if (i) __syncthreads();   // prior MAC must finish before Fs overwrite

            // ---- Features for this i ----
            for (int p = tid; p < FP; p += NTHREADS) {
                int gw = w0 + p;
                float xv = (gw < W_IN) ? x[(b * I_DIM + i) * W_IN + gw] : 0.0f;

                float* f = &Fs[p];
                f[0] = xv / (1.0f + __expf(-xv));

                float b0[11];
                #pragma unroll
                for (int j = 0; j < 11; j++)
                    b0[j] = (xv >= gridc(j) && xv < gridc(j + 1)) ? 1.0f : 0.0f;
                float b1[10];
                #pragma unroll
                for (int j = 0; j < 10; j++) {
                    float l = (xv - gridc(j))     * (1.0f / (gridc(j + 1) - gridc(j)));
                    float r = (gridc(j + 2) - xv) * (1.0f / (gridc(j + 2) - gridc(j + 1)));
                    b1[j] = l * b0[j] + r * b0[j + 1];
                }
                float b2[9];
                #pragma unroll
                for (int j = 0; j < 9; j++) {
                    float l = (xv - gridc(j))     * (1.0f / (gridc(j + 2) - gridc(j)));
                    float r = (gridc(j + 3) - xv) * (1.0f / (gridc(j + 3) - gridc(j + 1)));
                    b2[j] = l * b1[j] + r * b1[j + 1];
                }
                #pragma unroll
                for (int j = 0; j < 8; j++) {
                    float l = (xv - gridc(j))     * (1.0f / (gridc(j + 3) - gridc(j)));
                    float r = (gridc(j + 4) - xv) * (1.0f / (gridc(j + 4) - gridc(j + 1)));
                    f[(j + 1) * FP] = l * b2[j] + r * b2[j + 1];
                }
            }
            __syncthreads();

            // ---- MAC over this i ----
            #pragma unroll 3
            for (int c = 0; c < NC; c++) {
                const float* frow = Fs + c * FP + wt * 4;
                // group A: [wt*4, wt*4+8)      — lane stride 16B, conflict-free
                float4 a0 = *(const float4*)(frow);
                float4 a1 = *(const float4*)(frow + 4);
                // group B: [wt*4+128, wt*4+136)
                float4 c0 = *(const float4*)(frow + HALF_W);
                float4 c1 = *(const float4*)(frow + HALF_W + 4);

                unsigned long long fsA[8], fsB[8];
                fsA[0] = splat2(a0.x); fsA[1] = splat2(a0.y);
                fsA[2] = splat2(a0.z); fsA[3] = splat2(a0.w);
                fsA[4] = splat2(a1.x); fsA[5] = splat2(a1.y);
                fsA[6] = splat2(a1.z); fsA[7] = splat2(a1.w);
                fsB[0] = splat2(c0.x); fsB[1] = splat2(c0.y);
                fsB[2] = splat2(c0.z); fsB[3] = splat2(c0.w);
                fsB[4] = splat2(c1.x); fsB[5] = splat2(c1.y);
                fsB[6] = splat2(c1.z); fsB[7] = splat2(c1.w);

                #pragma unroll
                for (int k = 0; k < KSZ; k++) {
                    // two broadcast LDS.128: weight octet = 4 f32x2 pairs
                    const float* wrow = &Wc[((i * KSZ + k) * NC + c) * O_DIM + o0];
                    ulonglong2 wq0 = *(const ulonglong2*)(wrow);
                    ulonglong2 wq1 = *(const ulonglong2*)(wrow + 4);
                    #pragma unroll
                    for (int u = 0; u < 4; u++) {
                        ffma2(acc[0][0][u], wq0.x, fsA[u + k]);
                        ffma2(acc[0][1][u], wq0.y, fsA[u + k]);
                        ffma2(acc[0][2][u], wq1.x, fsA[u + k]);
                        ffma2(acc[0][3][u], wq1.y, fsA[u + k]);
                        ffma2(acc[1][0][u], wq0.x, fsB[u + k]);
                        ffma2(acc[1][1][u], wq0.y, fsB[u + k]);
                        ffma2(acc[1][2][u], wq1.x, fsB[u + k]);
                        ffma2(acc[1][3][u], wq1.y, fsB[u + k]);
                    }
                }
            }
        }

        // ---- Store. 8 o-rows x (2 groups x 4 w) per thread. ----
        #pragma unroll
        for (int g = 0; g < 2; g++) {
            const int wbase = w0 + wt * 4 + g * HALF_W;
            const bool full = (wbase + 4 <= W_OUT);
            #pragma unroll
            for (int p = 0; p < 4; p++) {
                float lv[4], hv[4];
                #pragma unroll
                for (int u = 0; u < 4; u++) {
                    lv[u] = lo32(acc[g][p][u]);
                    hv[u] = hi32(acc[g][p][u]);
                }
                int olo = o0 + 2 * p;
                float* rlo = out + ((size_t)(b * O_DIM + olo)) * W_OUT + wbase;
                float* rhi = rlo + W_OUT;
                if (full) {
                    *(float4*)rlo = make_float4(lv[0], lv[1], lv[2], lv[3]);
                    *(float4*)rhi = make_float4(hv[0], hv[1], hv[2], hv[3]);
                } else {
                    #pragma unroll
                    for (int u = 0; u < 4; u++) {
                        if (wbase + u < W_OUT) {
                            rlo[u] = lv[u];
                            rhi[u] = hv[u];
                        }
                    }
                }
            }
        }
    }
}

extern "C" void kernel_launch(void* const* d_in, const int* in_sizes, int n_in,
                              void* d_out, int out_size)
{
    const float* x             = (const float*)d_in[0];
    const float* base_weight   = (const float*)d_in[1];
    const float* spline_weight = (const float*)d_in[2];
    const float* spline_scaler = (const float*)d_in[3];
    float* out = (float*)d_out;

    reset_ctr<<<1, 1>>>();

    size_t smem_bytes = SMEM_FLOATS * sizeof(float);   // 55440
    cudaFuncSetAttribute(kan_conv1d_kernel,
                         cudaFuncAttributeMaxDynamicSharedMemorySize,
                         (int)smem_bytes);

    kan_conv1d_kernel<<<GRID_BLOCKS, NTHREADS, smem_bytes>>>(
        x, base_weight, spline_weight, spline_scaler, out);
}

// round 16
// speedup vs baseline: 1.1279x; 1.1279x over previous
#include <cuda_runtime.h>

// KAN 1-D conv, B=32 I=8 O=32 W=8192 K=5 Wo=8188, 9 channels (silu + 8 cubic B-splines).
// R16: R14 (8o x 8w tile, TILE_W=256, I_CHUNK=2, 444 stealing blocks) + local
// de Boor feature evaluation: only the 4 nonzero cubic bases are computed
// (~22 flops) instead of the full 27-value Cox-de-Boor table.

#define B_DIM 32
#define I_DIM 8
#define O_DIM 32
#define W_IN 8192
#define KSZ 5
#define W_OUT (W_IN - KSZ + 1)   // 8188
#define NC 9
#define TILE_W 256
#define HALF_W 128
#define FP (TILE_W + KSZ - 1)    // 260
#define NTHREADS 128
#define NTILES ((W_OUT + TILE_W - 1) / TILE_W)   // 32
#define NJOBS (NTILES * B_DIM)                   // 1024
#define I_CHUNK 2
#define N_PHASE (I_DIM / I_CHUNK)   // 4
#define NSM 148
#define GRID_BLOCKS (NSM * 3)       // 444 persistent-ish blocks

#define WC_ELEMS (I_DIM * KSZ * NC * O_DIM)    // 11520 floats = 46080 B
#define FS_ELEMS (I_CHUNK * NC * FP)           // 4680 floats  = 18720 B
#define SMEM_FLOATS (WC_ELEMS + FS_ELEMS)      // 16200 -> 64800 B (3 blocks/SM)

__device__ int g_tile_ctr;

__device__ __forceinline__ unsigned long long splat2(float f) {
    unsigned long long r;
    asm("mov.b64 %0, {%1, %1};" : "=l"(r) : "r"(__float_as_uint(f)));
    return r;
}
__device__ __forceinline__ void ffma2(unsigned long long& d,
                                      unsigned long long a,
                                      unsigned long long b) {
    asm("fma.rn.f32x2 %0, %1, %2, %0;" : "+l"(d) : "l"(a), "l"(b));
}
__device__ __forceinline__ float lo32(unsigned long long v) {
    return __uint_as_float((unsigned)(v & 0xffffffffull));
}
__device__ __forceinline__ float hi32(unsigned long long v) {
    return __uint_as_float((unsigned)(v >> 32));
}

__global__ void reset_ctr() { g_tile_ctr = 0; }

__global__ __launch_bounds__(NTHREADS, 3)
void kan_conv1d_kernel(const float* __restrict__ x,
                       const float* __restrict__ base_weight,
                       const float* __restrict__ spline_weight,
                       const float* __restrict__ spline_scaler,
                       float* __restrict__ out)
{
    extern __shared__ float smem[];
    float* Wc = smem;                 // [I][K][NC][O]  o contiguous
    float* Fs = smem + WC_ELEMS;      // [I_CHUNK][NC][FP]
    __shared__ int s_job;

    const int tid = threadIdx.x;

    // ---- Fuse weights into smem ONCE per block ----
    for (int idx = tid; idx < O_DIM * I_DIM * KSZ; idx += NTHREADS) {
        int k = idx % KSZ;
        int r = idx / KSZ;
        int i = r % I_DIM;
        int o = r / I_DIM;
        float bw = base_weight[idx];
        float sc = spline_scaler[idx];
        float* dst = &Wc[((i * KSZ + k) * NC) * O_DIM + o];
        dst[0] = bw;
        const float* sw = &spline_weight[idx * 8];
        #pragma unroll
        for (int c = 0; c < 8; c++)
            dst[(c + 1) * O_DIM] = sw[c] * sc;
    }

    const int wt = tid & 31;      // 32 w-lanes (warp-uniform og)
    const int og = tid >> 5;      // 4 o-groups of 8 o, one per warp
    const int o0 = og * 8;

    // ---- Job loop: steal (b, tile) pairs from the global counter ----
    while (true) {
        __syncthreads();
        if (tid == 0) s_job = atomicAdd(&g_tile_ctr, 1);
        __syncthreads();
        const int job = s_job;
        if (job >= NJOBS) break;

        const int b  = job >> 5;              // NTILES = 32
        const int w0 = (job & 31) * TILE_W;

        unsigned long long acc[2][4][4];
        #pragma unroll
        for (int g = 0; g < 2; g++)
            #pragma unroll
            for (int p = 0; p < 4; p++)
                #pragma unroll
                for (int u = 0; u < 4; u++)
                    acc[g][p][u] = 0ull;

        #pragma unroll 1
        for (int h = 0; h < N_PHASE; h++) {
            if (h) __syncthreads();

            // ---- Features for i in [h*I_CHUNK, (h+1)*I_CHUNK): local de Boor ----
            for (int e = tid; e < I_CHUNK * FP; e += NTHREADS) {
                int iL = e / FP;
                int p  = e % FP;
                int gw = w0 + p;
                int i  = h * I_CHUNK + iL;
                float xv = (gw < W_IN) ? x[(b * I_DIM + i) * W_IN + gw] : 0.0f;

                float* f = &Fs[iL * NC * FP + p];
                f[0] = xv / (1.0f + __expf(-xv));   // silu

                // knot interval: g(j) = (j-3)*0.4 - 1;  m: g(m) <= xv < g(m+1)
                int m = (int)floorf((xv + 2.2f) * 2.5f);
                m = m < 3 ? 3 : (m > 7 ? 7 : m);
                float gm = (float)(m - 3) * 0.4f - 1.0f;
                float dx = xv - gm;                 // in [0, 0.4]

                // degree 1 (2 nonzero)
                float n10 = (0.4f - dx) * 2.5f;     // B1_{m-1}
                float n11 = dx * 2.5f;              // B1_m
                // degree 2 (3 nonzero), spans = 0.8
                float n20 = (0.4f - dx) * 1.25f * n10;
                float n21 = (dx + 0.4f) * 1.25f * n10 + (0.8f - dx) * 1.25f * n11;
                float n22 = dx * 1.25f * n11;
                // degree 3 (4 nonzero), spans = 1.2
                const float c3 = 1.0f / 1.2f;
                float n30 = (0.4f - dx) * c3 * n20;
                float n31 = (dx + 0.8f) * c3 * n20 + (0.8f - dx) * c3 * n21;
                float n32 = (dx + 0.4f) * c3 * n21 + (1.2f - dx) * c3 * n22;
                float n33 = dx * c3 * n22;

                // zero all 8 spline channels, then scatter the 4 nonzero
                // (channels m-2 .. m+1; m in [3,7] keeps them within [1,8])
                #pragma unroll
                for (int c = 1; c <= 8; c++)
                    f[c * FP] = 0.0f;
                f[(m - 2) * FP] = n30;
                f[(m - 1) * FP] = n31;
                f[(m    ) * FP] = n32;
                f[(m + 1) * FP] = n33;
            }
            __syncthreads();

            // ---- MAC over this i-chunk (identical to R14) ----
            #pragma unroll 1
            for (int iL = 0; iL < I_CHUNK; iL++) {
                const int i = h * I_CHUNK + iL;
                #pragma unroll 3
                for (int c = 0; c < NC; c++) {
                    const float* frow = Fs + (iL * NC + c) * FP + wt * 4;
                    float4 a0 = *(const float4*)(frow);
                    float4 a1 = *(const float4*)(frow + 4);
                    float4 c0 = *(const float4*)(frow + HALF_W);
                    float4 c1 = *(const float4*)(frow + HALF_W + 4);

                    unsigned long long fsA[8], fsB[8];
                    fsA[0] = splat2(a0.x); fsA[1] = splat2(a0.y);
                    fsA[2] = splat2(a0.z); fsA[3] = splat2(a0.w);
                    fsA[4] = splat2(a1.x); fsA[5] = splat2(a1.y);
                    fsA[6] = splat2(a1.z); fsA[7] = splat2(a1.w);
                    fsB[0] = splat2(c0.x); fsB[1] = splat2(c0.y);
                    fsB[2] = splat2(c0.z); fsB[3] = splat2(c0.w);
                    fsB[4] = splat2(c1.x); fsB[5] = splat2(c1.y);
                    fsB[6] = splat2(c1.z); fsB[7] = splat2(c1.w);

                    #pragma unroll
                    for (int k = 0; k < KSZ; k++) {
                        const float* wrow = &Wc[((i * KSZ + k) * NC + c) * O_DIM + o0];
                        ulonglong2 wq0 = *(const ulonglong2*)(wrow);
                        ulonglong2 wq1 = *(const ulonglong2*)(wrow + 4);
                        #pragma unroll
                        for (int u = 0; u < 4; u++) {
                            ffma2(acc[0][0][u], wq0.x, fsA[u + k]);
                            ffma2(acc[0][1][u], wq0.y, fsA[u + k]);
                            ffma2(acc[0][2][u], wq1.x, fsA[u + k]);
                            ffma2(acc[0][3][u], wq1.y, fsA[u + k]);
                            ffma2(acc[1][0][u], wq0.x, fsB[u + k]);
                            ffma2(acc[1][1][u], wq0.y, fsB[u + k]);
                            ffma2(acc[1][2][u], wq1.x, fsB[u + k]);
                            ffma2(acc[1][3][u], wq1.y, fsB[u + k]);
                        }
                    }
                }
            }
        }

        // ---- Store. 8 o-rows x (2 groups x 4 w) per thread. ----
        #pragma unroll
        for (int g = 0; g < 2; g++) {
            const int wbase = w0 + wt * 4 + g * HALF_W;
            const bool full = (wbase + 4 <= W_OUT);
            #pragma unroll
            for (int p = 0; p < 4; p++) {
                float lv[4], hv[4];
                #pragma unroll
                for (int u = 0; u < 4; u++) {
                    lv[u] = lo32(acc[g][p][u]);
                    hv[u] = hi32(acc[g][p][u]);
                }
                int olo = o0 + 2 * p;
                float* rlo = out + ((size_t)(b * O_DIM + olo)) * W_OUT + wbase;
                float* rhi = rlo + W_OUT;
                if (full) {
                    *(float4*)rlo = make_float4(lv[0], lv[1], lv[2], lv[3]);
                    *(float4*)rhi = make_float4(hv[0], hv[1], hv[2], hv[3]);
                } else {
                    #pragma unroll
                    for (int u = 0; u < 4; u++) {
                        if (wbase + u < W_OUT) {
                            rlo[u] = lv[u];
                            rhi[u] = hv[u];
                        }
                    }
                }
            }
        }
    }
}

extern "C" void kernel_launch(void* const* d_in, const int* in_sizes, int n_in,
                              void* d_out, int out_size)
{
    const float* x             = (const float*)d_in[0];
    const float* base_weight   = (const float*)d_in[1];
    const float* spline_weight = (const float*)d_in[2];
    const float* spline_scaler = (const float*)d_in[3];
    float* out = (float*)d_out;

    reset_ctr<<<1, 1>>>();

    size_t smem_bytes = SMEM_FLOATS * sizeof(float);   // 64800
    cudaFuncSetAttribute(kan_conv1d_kernel,
                         cudaFuncAttributeMaxDynamicSharedMemorySize,
                         (int)smem_bytes);

    kan_conv1d_kernel<<<GRID_BLOCKS, NTHREADS, smem_bytes>>>(
        x, base_weight, spline_weight, spline_scaler, out);
}